// round 12
// baseline (speedup 1.0000x reference)
#include <cuda_runtime.h>
#include <math.h>
#include <stdint.h>

// out[b,k] = exp(-beta_k * max(||x_b||^2 + ||c_k||^2 - 2 x_b.c_k, 0))
// B=16384, K=4096, D=1024, fp32.
//
// fp32 exp(-t) == exactly 0.0f for t > ~104. Cauchy-Schwarz: d2 >= (||x_b||-||c_k||)^2.
// Per-column interval [lo_k, hi_k] of ||x|| for which an element is NOT provably
// zero; global interval over k. Rows with ||x_b|| outside the global interval are
// provably all-zero.
//
// Store-path findings on this chip (R1..R11): per-thread STG caps at ~770 GB/s
// (best shape) or ~225 GB/s (loops / CE memset), DRAM idle throughout -> the wall
// is the LSU store pipeline, not DRAM. This round routes the bulk zero-fill
// through TMA (cp.async.bulk shared->global, ~6300 B/cyc chip cap, same LTS path
// as reads): one block per row zeroes a 16KB smem tile once and issues a single
// bulk store for the whole row. Rare non-provable rows take the exact
// interval-test + fp32 dot + expf path with regular stores.

#define B_ROWS 16384
#define K_COLS 4096
#define D_DIM  1024
#define THRESH 106.0f
#define ROW_BYTES (K_COLS * 4)   // 16384

__device__ float g_x2[B_ROWS];
__device__ float g_rx[B_ROWS];
__device__ float g_c2[K_COLS];
__device__ float g_lo[K_COLS];
__device__ float g_hi[K_COLS];
__device__ float g_glo;
__device__ float g_ghi;

// ---------------------------------------------------------------------------
// Kernel 1: row norms. Rows [0,K): centers -> c2, lo, hi. Rows [K,K+B): x -> x2, rx.
// ---------------------------------------------------------------------------
__global__ void __launch_bounds__(256) norms_kernel(const float* __restrict__ x,
                                                    const float* __restrict__ c,
                                                    const float* __restrict__ betas) {
    const int row = blockIdx.x;
    const bool is_center = (row < K_COLS);
    const float* src = is_center ? (c + (size_t)row * D_DIM)
                                 : (x + (size_t)(row - K_COLS) * D_DIM);
    const int tid = threadIdx.x;
    float4 a = reinterpret_cast<const float4*>(src)[tid];
    float s = a.x * a.x + a.y * a.y + a.z * a.z + a.w * a.w;
    #pragma unroll
    for (int o = 16; o > 0; o >>= 1)
        s += __shfl_xor_sync(0xffffffffu, s, o);
    __shared__ float ws[8];
    if ((tid & 31) == 0) ws[tid >> 5] = s;
    __syncthreads();
    if (tid == 0) {
        float t = 0.f;
        #pragma unroll
        for (int i = 0; i < 8; i++) t += ws[i];
        if (is_center) {
            g_c2[row] = t;
            const float beta = betas[row];
            const float sk = sqrtf(t);
            float lo = -INFINITY, hi = INFINITY;
            if (beta > 0.0f && isfinite(sk)) {
                const float rk = sqrtf(THRESH / beta);
                if (isfinite(rk)) { lo = sk - rk; hi = sk + rk; }
            }
            if (!(lo == lo)) lo = -INFINITY;   // NaN -> always-exact interval
            if (!(hi == hi)) hi =  INFINITY;
            g_lo[row] = lo;
            g_hi[row] = hi;
        } else {
            g_x2[row - K_COLS] = t;
            g_rx[row - K_COLS] = sqrtf(t);
        }
    }
}

// ---------------------------------------------------------------------------
// Kernel 2: global interval reduce.
// ---------------------------------------------------------------------------
__global__ void __launch_bounds__(256) glob_kernel() {
    __shared__ float slo[256], shi[256];
    float lo = INFINITY, hi = -INFINITY;
    for (int k = threadIdx.x; k < K_COLS; k += 256) {
        lo = fminf(lo, g_lo[k]);
        hi = fmaxf(hi, g_hi[k]);
    }
    slo[threadIdx.x] = lo;
    shi[threadIdx.x] = hi;
    __syncthreads();
    for (int s2 = 128; s2 > 0; s2 >>= 1) {
        if (threadIdx.x < s2) {
            slo[threadIdx.x] = fminf(slo[threadIdx.x], slo[threadIdx.x + s2]);
            shi[threadIdx.x] = fmaxf(shi[threadIdx.x], shi[threadIdx.x + s2]);
        }
        __syncthreads();
    }
    if (threadIdx.x == 0) { g_glo = slo[0]; g_ghi = shi[0]; }
}

// ---------------------------------------------------------------------------
// Kernel 3: main. One block per row (grid 16384, 256 threads).
// Common path: zero a 16KB smem tile, ONE bulk TMA store covers the whole row
// (store pipeline bypassed; TMA/LTS path). Rare path: exact recompute with STG.
// ---------------------------------------------------------------------------
__global__ void __launch_bounds__(256) rbf_tma_main(const float* __restrict__ x,
                                                    const float* __restrict__ c,
                                                    const float* __restrict__ betas,
                                                    float* __restrict__ out) {
    const int tid = threadIdx.x;
    const int b   = blockIdx.x;
    float* __restrict__ orow = out + (size_t)b * K_COLS;

    const float t = g_rx[b];
    if (t < g_glo || t > g_ghi) {
        // Provably-zero row: zero smem tile, single 16KB bulk TMA store.
        __shared__ __align__(128) float4 zs[K_COLS / 4];   // 16KB
        const float4 z = make_float4(0.f, 0.f, 0.f, 0.f);
        zs[tid]       = z;
        zs[tid + 256] = z;
        zs[tid + 512] = z;
        zs[tid + 768] = z;
        __syncthreads();
        if (tid == 0) {
            uint32_t saddr;
            asm("{ .reg .u64 tt; cvta.to.shared.u64 tt, %1; cvt.u32.u64 %0, tt; }"
                : "=r"(saddr) : "l"(zs));
            asm volatile("fence.proxy.async.shared::cta;" ::: "memory");
            asm volatile(
                "cp.async.bulk.global.shared::cta.bulk_group [%0], [%1], %2;"
                :: "l"(orow), "r"(saddr), "r"(ROW_BYTES) : "memory");
            asm volatile("cp.async.bulk.commit_group;" ::: "memory");
            asm volatile("cp.async.bulk.wait_group 0;" ::: "memory");
        }
        return;
    }

    // Exact path (block-uniform branch; statistically ~1e-3 of rows).
    __shared__ float xs[D_DIM];
    reinterpret_cast<float4*>(xs)[tid] =
        reinterpret_cast<const float4*>(x + (size_t)b * D_DIM)[tid];
    __syncthreads();
    const float sx = g_x2[b];
    float4* __restrict__ orow4 = reinterpret_cast<float4*>(orow);

    #pragma unroll
    for (int j = 0; j < 4; j++) {
        const int kq = tid + 256 * j;                       // float4 column group
        const float4 lo4 = reinterpret_cast<const float4*>(g_lo)[kq];
        const float4 hi4 = reinterpret_cast<const float4*>(g_hi)[kq];
        const float4 c24 = reinterpret_cast<const float4*>(g_c2)[kq];
        const float4 bt4 = reinterpret_cast<const float4*>(betas)[kq];
        const float lo_a[4] = {lo4.x, lo4.y, lo4.z, lo4.w};
        const float hi_a[4] = {hi4.x, hi4.y, hi4.z, hi4.w};
        const float c2_a[4] = {c24.x, c24.y, c24.z, c24.w};
        const float bt_a[4] = {bt4.x, bt4.y, bt4.z, bt4.w};
        float o[4];
        #pragma unroll
        for (int q = 0; q < 4; q++) {
            if (t < lo_a[q] || t > hi_a[q]) {
                o[q] = 0.0f;                                // provably underflows
            } else {
                const float* __restrict__ cr = c + (size_t)(kq * 4 + q) * D_DIM;
                float dot = 0.f;
                #pragma unroll 8
                for (int i = 0; i < D_DIM; i++) dot = fmaf(xs[i], cr[i], dot);
                const float d2 = fmaxf(sx + c2_a[q] - 2.0f * dot, 0.0f);
                o[q] = expf(-bt_a[q] * d2);
            }
        }
        orow4[kq] = make_float4(o[0], o[1], o[2], o[3]);
    }
}

// ---------------------------------------------------------------------------
extern "C" void kernel_launch(void* const* d_in, const int* in_sizes, int n_in,
                              void* d_out, int out_size) {
    const float* x     = (const float*)d_in[0];
    const float* cent  = (const float*)d_in[1];
    const float* betas = (const float*)d_in[2];
    float* out = (float*)d_out;

    norms_kernel<<<K_COLS + B_ROWS, 256>>>(x, cent, betas);
    glob_kernel<<<1, 256>>>();
    rbf_tma_main<<<B_ROWS, 256>>>(x, cent, betas, out);
}

// round 15
// speedup vs baseline: 3.0271x; 3.0271x over previous
#include <cuda_runtime.h>
#include <math.h>
#include <stdint.h>

// out[b,k] = exp(-beta_k * max(||x_b||^2 + ||c_k||^2 - 2 x_b.c_k, 0))
// B=16384, K=4096, D=1024, fp32.
//
// fp32 exp(-t) == exactly 0.0f for t > ~104. Cauchy-Schwarz: d2 >= (||x_b||-||c_k||)^2.
// Per-column interval [lo_k, hi_k] of ||x|| for which an element is NOT provably
// zero; global interval over k. Rows with ||x_b|| outside the global interval are
// provably all-zero (true for this data; exact fallback otherwise).
//
// Store-path law measured on this chip (R1..R12):
//   - flat shape (65536 CTAs, ONE vector store per thread, exit): ~770 GB/s
//   - looped STG / CE memset / TMA bulk store: 150-225 GB/s
// DRAM idle in all cases -> per-thread/issue overhead regime. This round keeps
// the proven flat shape but doubles bytes/thread via 256-bit stores
// (st.global.v8.f32, sm_100+): 128 threads/block, one STG.256 each.

#define B_ROWS 16384
#define K_COLS 4096
#define D_DIM  1024
#define THRESH 106.0f

__device__ float g_x2[B_ROWS];
__device__ float g_rx[B_ROWS];
__device__ float g_c2[K_COLS];
__device__ float g_lo[K_COLS];
__device__ float g_hi[K_COLS];
__device__ float g_glo;
__device__ float g_ghi;

// ---------------------------------------------------------------------------
// Kernel 1: row norms. Rows [0,K): centers -> c2, lo, hi. Rows [K,K+B): x -> x2, rx.
// ---------------------------------------------------------------------------
__global__ void __launch_bounds__(256) norms_kernel(const float* __restrict__ x,
                                                    const float* __restrict__ c,
                                                    const float* __restrict__ betas) {
    const int row = blockIdx.x;
    const bool is_center = (row < K_COLS);
    const float* src = is_center ? (c + (size_t)row * D_DIM)
                                 : (x + (size_t)(row - K_COLS) * D_DIM);
    const int tid = threadIdx.x;
    float4 a = reinterpret_cast<const float4*>(src)[tid];
    float s = a.x * a.x + a.y * a.y + a.z * a.z + a.w * a.w;
    #pragma unroll
    for (int o = 16; o > 0; o >>= 1)
        s += __shfl_xor_sync(0xffffffffu, s, o);
    __shared__ float ws[8];
    if ((tid & 31) == 0) ws[tid >> 5] = s;
    __syncthreads();
    if (tid == 0) {
        float t = 0.f;
        #pragma unroll
        for (int i = 0; i < 8; i++) t += ws[i];
        if (is_center) {
            g_c2[row] = t;
            const float beta = betas[row];
            const float sk = sqrtf(t);
            float lo = -INFINITY, hi = INFINITY;
            if (beta > 0.0f && isfinite(sk)) {
                const float rk = sqrtf(THRESH / beta);
                if (isfinite(rk)) { lo = sk - rk; hi = sk + rk; }
            }
            if (!(lo == lo)) lo = -INFINITY;   // NaN -> always-exact interval
            if (!(hi == hi)) hi =  INFINITY;
            g_lo[row] = lo;
            g_hi[row] = hi;
        } else {
            g_x2[row - K_COLS] = t;
            g_rx[row - K_COLS] = sqrtf(t);
        }
    }
}

// ---------------------------------------------------------------------------
// Kernel 2: global interval reduce.
// ---------------------------------------------------------------------------
__global__ void __launch_bounds__(256) glob_kernel() {
    __shared__ float slo[256], shi[256];
    float lo = INFINITY, hi = -INFINITY;
    for (int k = threadIdx.x; k < K_COLS; k += 256) {
        lo = fminf(lo, g_lo[k]);
        hi = fmaxf(hi, g_hi[k]);
    }
    slo[threadIdx.x] = lo;
    shi[threadIdx.x] = hi;
    __syncthreads();
    for (int s2 = 128; s2 > 0; s2 >>= 1) {
        if (threadIdx.x < s2) {
            slo[threadIdx.x] = fminf(slo[threadIdx.x], slo[threadIdx.x + s2]);
            shi[threadIdx.x] = fmaxf(shi[threadIdx.x], shi[threadIdx.x + s2]);
        }
        __syncthreads();
    }
    if (threadIdx.x == 0) { g_glo = slo[0]; g_ghi = shi[0]; }
}

// ---------------------------------------------------------------------------
// Kernel 3: main. Grid (4, B), 128 threads. Block (chunk,b) owns 1024 columns
// of row b; each thread owns 8 consecutive floats (32B, aligned).
// Fast path: ONE st.global.v8.f32 of zeros, exit.
// Slow path (block-uniform, rare): exact interval test + fp32 dot + expf.
// ---------------------------------------------------------------------------
__global__ void __launch_bounds__(128) rbf_main(const float* __restrict__ x,
                                                const float* __restrict__ c,
                                                const float* __restrict__ betas,
                                                float* __restrict__ out) {
    const int tid   = threadIdx.x;
    const int b     = blockIdx.y;
    const int kbase = blockIdx.x * 1024 + tid * 8;
    float* __restrict__ optr = out + (size_t)b * K_COLS + kbase;

    const float t = g_rx[b];
    if (t < g_glo || t > g_ghi) {
        // provably-zero row: single 256-bit store, done. (NaN t falls through)
        const float z = 0.0f;
        asm volatile(
            "st.global.v8.f32 [%0], {%1,%2,%3,%4,%5,%6,%7,%8};"
            :: "l"(optr), "f"(z), "f"(z), "f"(z), "f"(z),
               "f"(z), "f"(z), "f"(z), "f"(z)
            : "memory");
        return;
    }

    // Exact path (block-uniform branch; statistically ~1e-3 of rows).
    __shared__ float xs[D_DIM];
    // 128 threads stage 1024 floats: two float4 each.
    reinterpret_cast<float4*>(xs)[tid] =
        reinterpret_cast<const float4*>(x + (size_t)b * D_DIM)[tid];
    reinterpret_cast<float4*>(xs)[tid + 128] =
        reinterpret_cast<const float4*>(x + (size_t)b * D_DIM)[tid + 128];
    __syncthreads();
    const float sx = g_x2[b];

    float o[8];
    #pragma unroll
    for (int h = 0; h < 2; h++) {
        const int kq = (kbase >> 2) + h;                    // float4 column group
        const float4 lo4 = reinterpret_cast<const float4*>(g_lo)[kq];
        const float4 hi4 = reinterpret_cast<const float4*>(g_hi)[kq];
        const float4 c24 = reinterpret_cast<const float4*>(g_c2)[kq];
        const float4 bt4 = reinterpret_cast<const float4*>(betas)[kq];
        const float lo_a[4] = {lo4.x, lo4.y, lo4.z, lo4.w};
        const float hi_a[4] = {hi4.x, hi4.y, hi4.z, hi4.w};
        const float c2_a[4] = {c24.x, c24.y, c24.z, c24.w};
        const float bt_a[4] = {bt4.x, bt4.y, bt4.z, bt4.w};
        #pragma unroll
        for (int q = 0; q < 4; q++) {
            const int kk = kq * 4 + q;
            if (t < lo_a[q] || t > hi_a[q]) {
                o[h * 4 + q] = 0.0f;                        // provably underflows
            } else {
                const float* __restrict__ cr = c + (size_t)kk * D_DIM;
                float dot = 0.f;
                #pragma unroll 8
                for (int i = 0; i < D_DIM; i++) dot = fmaf(xs[i], cr[i], dot);
                const float d2 = fmaxf(sx + c2_a[q] - 2.0f * dot, 0.0f);
                o[h * 4 + q] = expf(-bt_a[q] * d2);
            }
        }
    }
    asm volatile(
        "st.global.v8.f32 [%0], {%1,%2,%3,%4,%5,%6,%7,%8};"
        :: "l"(optr), "f"(o[0]), "f"(o[1]), "f"(o[2]), "f"(o[3]),
           "f"(o[4]), "f"(o[5]), "f"(o[6]), "f"(o[7])
        : "memory");
}

// ---------------------------------------------------------------------------
extern "C" void kernel_launch(void* const* d_in, const int* in_sizes, int n_in,
                              void* d_out, int out_size) {
    const float* x     = (const float*)d_in[0];
    const float* cent  = (const float*)d_in[1];
    const float* betas = (const float*)d_in[2];
    float* out = (float*)d_out;

    norms_kernel<<<K_COLS + B_ROWS, 256>>>(x, cent, betas);
    glob_kernel<<<1, 256>>>();
    dim3 grid(K_COLS / 1024, B_ROWS);
    rbf_main<<<grid, 128>>>(x, cent, betas, out);
}